// round 10
// baseline (speedup 1.0000x reference)
#include <cuda_runtime.h>
#include <cuda_bf16.h>

// WTA2D: per (B,C) row of H*W=3136 fp32, t = 313th-largest, out = (t > x) ? x : 0.
//
// One CTA (256 thr) per row, 16 raw uint keys/thread in registers.
// Round 1: 256-bucket shared atomic histogram of raw top byte, 2 interleaved
//          copies (bucket*2 + lane&1) to halve same-address conflict degree;
//          key-order permutation folded into the warp-0 pick walk.
// Round 2: same trick on the sign-folded 2nd byte over the winning bucket
//          (pre-zeroed second half of the hist array -> no extra barrier).
// Tail: gather <=64 candidates; PARALLEL rank-count (64 threads x 64 compares)
//       replaces the serial bit bisection. Fallback: iterate byte rounds.

#define NROW 3136
#define KSEL 313u

__device__ __forceinline__ unsigned u2k(unsigned u) {
    return (u & 0x80000000u) ? ~u : (u | 0x80000000u);
}
__device__ __forceinline__ float k2f(unsigned k) {
    unsigned u = (k & 0x80000000u) ? (k ^ 0x80000000u) : ~k;
    return __uint_as_float(u);
}

__global__ void __launch_bounds__(256, 6)
wta2d_kernel(const float* __restrict__ x, float* __restrict__ out) {
    const int tid  = threadIdx.x;
    const int lane = tid & 31;
    const int warp = tid >> 5;
    const size_t base = (size_t)blockIdx.x * NROW;

    __shared__ unsigned hist[1024];   // [0,512): round1 x2 copies; [512,1024): round2
    __shared__ unsigned gbuf[64];
    __shared__ unsigned sb_d, sb_rank, sb_m;
    __shared__ float sb_t;
    __shared__ int gcount;

    reinterpret_cast<uint4*>(hist)[tid] = make_uint4(0u, 0u, 0u, 0u);
    if (tid < 64) gbuf[tid] = 0u;     // zero-pad for the rank tail
    if (tid == 0) gcount = 0;

    // ---- load row -> raw bits in registers ----
    unsigned u[16];
    const bool has4 = (tid < 16);
    const uint4* xin = reinterpret_cast<const uint4*>(x + base);
#pragma unroll
    for (int s = 0; s < 4; ++s) {
        int p = tid + s * 256;
        if (s < 3 || has4) {
            uint4 f = xin[p];
            u[4*s+0] = f.x; u[4*s+1] = f.y; u[4*s+2] = f.z; u[4*s+3] = f.w;
        } else {
            u[4*s+0] = u[4*s+1] = u[4*s+2] = u[4*s+3] = 0u;
        }
    }
    __syncthreads();                  // zeros visible

    const unsigned p2 = (unsigned)(lane & 1);

    // ---- round 1: raw top-byte histogram, 2 interleaved copies ----
#pragma unroll
    for (int j = 0; j < 16; ++j) {
        bool valid = (j < 12) || has4;
        if (valid) atomicAdd(&hist[((u[j] >> 24) << 1) | p2], 1u);
    }
    __syncthreads();

    if (warp == 0) {
        // ordered slot o (0 = highest key): o<128 -> u8=127-o, else u8=o
        int o0 = lane * 8;
        unsigned cc[8];
#pragma unroll
        for (int j = 0; j < 8; ++j) {
            int o = o0 + j;
            int u8 = (o < 128) ? (127 - o) : o;
            uint2 h = reinterpret_cast<const uint2*>(hist)[u8];
            cc[j] = h.x + h.y;
        }
        unsigned tot = cc[0]+cc[1]+cc[2]+cc[3]+cc[4]+cc[5]+cc[6]+cc[7];
        unsigned p = tot;             // inclusive prefix over lanes (o ascending)
#pragma unroll
        for (int off = 1; off <= 16; off <<= 1) {
            unsigned v = __shfl_up_sync(0xFFFFFFFFu, p, off);
            if (lane >= off) p += v;
        }
        unsigned run = p - tot;       // counts at higher keys
#pragma unroll
        for (int j = 0; j < 8; ++j) {
            unsigned nr = run + cc[j];
            if (nr >= KSEL && run < KSEL) {
                int o = o0 + j;
                unsigned u8 = (o < 128) ? (unsigned)(127 - o) : (unsigned)o;
                sb_d    = u8 | ((o >= 128) ? 256u : 0u);
                sb_rank = KSEL - run;
                sb_m    = cc[j];
            }
            run = nr;
        }
    }
    __syncthreads();

    const unsigned X = (sb_d & 256u) ? 0xFFu : 0u;   // sign fold for lower bytes
    unsigned U  = sb_d & 0xFFu;       // raw prefix
    unsigned rk = sb_rank;
    unsigned m  = sb_m;
    int bits = 24;                    // unresolved low bits
    bool zeroed = true;               // [512,1024) pre-zeroed for first loop round

    // ---- byte rounds while bucket too big ----
    while (m > 64u && bits > 0) {
        if (!zeroed) {
            hist[512 + tid] = 0u;
            hist[768 + tid] = 0u;
            __syncthreads();
        }
        zeroed = false;
#pragma unroll
        for (int j = 0; j < 16; ++j) {
            bool valid = (j < 12) || has4;
            if (valid && (u[j] >> bits) == U)
                atomicAdd(&hist[512 + (((((u[j] >> (bits - 8)) & 0xFFu) ^ X) << 1) | p2)], 1u);
        }
        __syncthreads();
        if (warp == 0) {              // descending pick over 256 key-byte buckets
            unsigned rcur = rk;
            unsigned cc[8];
#pragma unroll
            for (int j = 0; j < 8; ++j) {
                uint2 h = reinterpret_cast<const uint2*>(hist)[256 + lane * 8 + j];
                cc[j] = h.x + h.y;
            }
            unsigned tot = cc[0]+cc[1]+cc[2]+cc[3]+cc[4]+cc[5]+cc[6]+cc[7];
            unsigned s = tot;
#pragma unroll
            for (int off = 1; off <= 16; off <<= 1) {
                unsigned v = __shfl_down_sync(0xFFFFFFFFu, s, off);
                if (lane + off < 32) s += v;
            }
            unsigned run = s - tot;   // counts in higher buckets
#pragma unroll
            for (int j = 7; j >= 0; --j) {
                unsigned nr = run + cc[j];
                if (nr >= rcur && run < rcur) {
                    sb_d    = (unsigned)(lane * 8 + j);   // key byte
                    sb_rank = rcur - run;
                    sb_m    = cc[j];
                }
                run = nr;
            }
        }
        __syncthreads();
        U  = (U << 8) | (sb_d ^ X);
        rk = sb_rank;
        m  = sb_m;
        bits -= 8;
    }

    // ---- tail ----
    if (m <= 64u) {
        // gather candidates (key transform only here)
#pragma unroll
        for (int j = 0; j < 16; ++j) {
            bool valid = (j < 12) || has4;
            if (valid && (u[j] >> bits) == U)
                gbuf[atomicAdd(&gcount, 1)] = u2k(u[j]);
        }
        __syncthreads();
        if (tid < 64) {               // parallel rank count (warps 0,1)
            int n = gcount;
            if (tid < n) {
                unsigned k = gbuf[tid];
                unsigned g = 0, e = 0;
#pragma unroll
                for (int q = 0; q < 16; ++q) {
                    uint4 v = reinterpret_cast<const uint4*>(gbuf)[q];  // broadcast
                    g += (v.x > k) + (v.y > k) + (v.z > k) + (v.w > k);
                    e += (v.x == k) + (v.y == k) + (v.z == k) + (v.w == k);
                }
                if (g < rk && rk <= g + e) sb_t = k2f(k);   // same value if multi-writer
            }
        }
        __syncthreads();
    } else {
        // bits == 0: full raw value resolved (mass ties)
        if (tid == 0) sb_t = __uint_as_float(U);
        __syncthreads();
    }
    const float t = sb_t;

    // ---- mask + store: float compare ----
    float4* po = reinterpret_cast<float4*>(out + base);
#pragma unroll
    for (int s = 0; s < 4; ++s) {
        int p = tid + s * 256;
        if (s < 3 || has4) {
            float4 o;
            float fx = __uint_as_float(u[4*s+0]);
            float fy = __uint_as_float(u[4*s+1]);
            float fz = __uint_as_float(u[4*s+2]);
            float fw = __uint_as_float(u[4*s+3]);
            o.x = (fx < t) ? fx : 0.0f;
            o.y = (fy < t) ? fy : 0.0f;
            o.z = (fz < t) ? fz : 0.0f;
            o.w = (fw < t) ? fw : 0.0f;
            po[p] = o;
        }
    }
}

extern "C" void kernel_launch(void* const* d_in, const int* in_sizes, int n_in,
                              void* d_out, int out_size) {
    const float* x = (const float*)d_in[0];
    float* out = (float*)d_out;
    int rows = in_sizes[0] / NROW;   // 16384
    wta2d_kernel<<<rows, 256>>>(x, out);
}

// round 11
// speedup vs baseline: 1.0748x; 1.0748x over previous
#include <cuda_runtime.h>
#include <cuda_bf16.h>

// WTA2D: per (B,C) row of H*W=3136 fp32, t = 313th-largest, out = (t > x) ? x : 0.
//
// One CTA (256 thr) per row, 16 raw uint keys/thread in registers.
// FAST PATH (distribution-aware, exactness preserved by fallback):
//   The rank-313 threshold of N(0,1) rows lies in [1.0, 2.0). For that window
//   (u>>13)&0x3FF is a monotone 10-bit index -> ONE 1024-bucket shared atomic
//   histogram over ~27% of elements; elements >= 2.0 are counted and subtracted
//   from the rank; elements < 1.0 ignored. Pick crossing bucket (block scan),
//   gather its ~1-5 elements, tiny rank-count tail.
// FALLBACK (block-uniform flag): generic iterated byte-histogram rounds
//   (raw domain, sign fold) + ballot bisection — exact for any input.

#define NROW 3136
#define KSEL 313u
#define WLO 0x3F800000u    // 1.0f
#define WHI 0x40000000u    // 2.0f

__device__ __forceinline__ unsigned u2k(unsigned u) {
    return (u & 0x80000000u) ? ~u : (u | 0x80000000u);
}
__device__ __forceinline__ float k2f(unsigned k) {
    unsigned u = (k & 0x80000000u) ? (k ^ 0x80000000u) : ~k;
    return __uint_as_float(u);
}

__global__ void __launch_bounds__(256, 6)
wta2d_kernel(const float* __restrict__ x, float* __restrict__ out) {
    const int tid  = threadIdx.x;
    const int lane = tid & 31;
    const int warp = tid >> 5;
    const size_t base = (size_t)blockIdx.x * NROW;

    __shared__ unsigned hist[1024];
    __shared__ unsigned aboveW[8], pickW[8];
    __shared__ unsigned gbuf[64];
    __shared__ unsigned sb_b, sb_rank, sb_m;
    __shared__ float sb_t;
    __shared__ int gcount;

    reinterpret_cast<uint4*>(hist)[tid] = make_uint4(0u, 0u, 0u, 0u);
    if (tid < 64) gbuf[tid] = 0u;
    if (tid == 0) { gcount = 0; sb_m = 0u; }

    // ---- load row -> raw bits in registers ----
    unsigned u[16];
    const bool has4 = (tid < 16);
    const uint4* xin = reinterpret_cast<const uint4*>(x + base);
#pragma unroll
    for (int s = 0; s < 4; ++s) {
        int p = tid + s * 256;
        if (s < 3 || has4) {
            uint4 f = xin[p];
            u[4*s+0] = f.x; u[4*s+1] = f.y; u[4*s+2] = f.z; u[4*s+3] = f.w;
        } else {
            u[4*s+0] = u[4*s+1] = u[4*s+2] = u[4*s+3] = 0u;
        }
    }
    __syncthreads();                       // zeros visible

    // ---- classify: count >=2.0, histogram [1.0, 2.0) window ----
    unsigned ab = 0;
#pragma unroll
    for (int j = 0; j < 16; ++j) {
        bool valid = (j < 12) || has4;
        unsigned v = u[j];
        if (valid) {
            if (v < 0x80000000u && v >= WHI) ++ab;
            else if (v >= WLO && v < WHI)
                atomicAdd(&hist[(v >> 13) & 0x3FFu], 1u);
        }
    }
#pragma unroll
    for (int off = 16; off >= 1; off >>= 1)
        ab += __shfl_xor_sync(0xFFFFFFFFu, ab, off);
    if (lane == 0) aboveW[warp] = ab;
    __syncthreads();                       // hist + aboveW ready

    unsigned above = 0;
#pragma unroll
    for (int w = 0; w < 8; ++w) above += aboveW[w];

    bool fb = (above >= KSEL);             // block-uniform
    unsigned bsel = 0, rin = 0, m = 0;

    if (!fb) {
        const unsigned rk = KSEL - above;
        // pick crossing bucket among 1024 (thread owns 4: hist[tid*4..])
        uint4 h = reinterpret_cast<const uint4*>(hist)[tid];
        unsigned cc[4] = { h.x, h.y, h.z, h.w };
        unsigned tot = cc[0] + cc[1] + cc[2] + cc[3];
        unsigned s = tot;                  // warp suffix-inclusive (higher lanes = higher values)
#pragma unroll
        for (int off = 1; off <= 16; off <<= 1) {
            unsigned v = __shfl_down_sync(0xFFFFFFFFu, s, off);
            if (lane + off < 32) s += v;
        }
        if (lane == 0) pickW[warp] = s;
        __syncthreads();
        unsigned run = s - tot;            // counts at higher values
#pragma unroll
        for (int w = 0; w < 8; ++w) if (w > warp) run += pickW[w];
#pragma unroll
        for (int j = 3; j >= 0; --j) {     // walk own buckets high -> low
            unsigned nr = run + cc[j];
            if (nr >= rk && run < rk) {
                sb_b    = (unsigned)(tid * 4 + j);
                sb_rank = rk - run;
                sb_m    = cc[j];
            }
            run = nr;
        }
        __syncthreads();
        fb   = (sb_m == 0u);               // rank not inside window
        bsel = sb_b; rin = sb_rank; m = sb_m;
    }

    if (!fb && m <= 64u) {
        // ---- gather bucket elements, rank-count tail ----
#pragma unroll
        for (int j = 0; j < 16; ++j) {
            bool valid = (j < 12) || has4;
            unsigned v = u[j];
            if (valid && v >= WLO && v < WHI && ((v >> 13) & 0x3FFu) == bsel) {
                int p = atomicAdd(&gcount, 1);
                if (p < 64) gbuf[p] = v;   // raw bits; all positives -> u order = value order
            }
        }
        __syncthreads();
        if (gcount <= 64) {
            if (tid < 64) {
                int n = gcount;
                if (tid < n) {
                    unsigned k = gbuf[tid];
                    unsigned g = 0, e = 0;
#pragma unroll
                    for (int q = 0; q < 16; ++q) {
                        uint4 v = reinterpret_cast<const uint4*>(gbuf)[q];   // broadcast
                        g += (v.x > k) + (v.y > k) + (v.z > k) + (v.w > k);
                        e += (v.x == k) + (v.y == k) + (v.z == k) + (v.w == k);
                    }
                    if (g < rin && rin <= g + e) sb_t = __uint_as_float(k);
                }
            }
            __syncthreads();
        } else fb = true;
    } else if (!fb) fb = true;

    // ---- generic fallback: iterated byte rounds (exact, any input) ----
    if (fb) {
        hist[tid] = 0u;                    // entries 0..255 used
        if (tid == 0) gcount = 0;
        __syncthreads();
#pragma unroll
        for (int j = 0; j < 16; ++j) {
            bool valid = (j < 12) || has4;
            if (valid) atomicAdd(&hist[u[j] >> 24], 1u);
        }
        __syncthreads();
        if (warp == 0) {                   // ordered pick over raw top byte
            int o0 = lane * 8;
            unsigned cc[8];
#pragma unroll
            for (int j = 0; j < 8; ++j) {
                int o = o0 + j;
                int u8 = (o < 128) ? (127 - o) : o;
                cc[j] = hist[u8];
            }
            unsigned tot = cc[0]+cc[1]+cc[2]+cc[3]+cc[4]+cc[5]+cc[6]+cc[7];
            unsigned p = tot;
#pragma unroll
            for (int off = 1; off <= 16; off <<= 1) {
                unsigned v = __shfl_up_sync(0xFFFFFFFFu, p, off);
                if (lane >= off) p += v;
            }
            unsigned run = p - tot;
#pragma unroll
            for (int j = 0; j < 8; ++j) {
                unsigned nr = run + cc[j];
                if (nr >= KSEL && run < KSEL) {
                    int o = o0 + j;
                    unsigned u8 = (o < 128) ? (unsigned)(127 - o) : (unsigned)o;
                    sb_b    = u8 | ((o >= 128) ? 256u : 0u);
                    sb_rank = KSEL - run;
                    sb_m    = cc[j];
                }
                run = nr;
            }
        }
        __syncthreads();
        const unsigned X = (sb_b & 256u) ? 0xFFu : 0u;
        unsigned U  = sb_b & 0xFFu;
        unsigned K  = X ? (255u - U) : (U + 128u);
        unsigned rk = sb_rank;
        unsigned mm = sb_m;
        int bits = 24;
        while (mm > 64u && bits > 0) {
            hist[tid] = 0u;
            __syncthreads();
#pragma unroll
            for (int j = 0; j < 16; ++j) {
                bool valid = (j < 12) || has4;
                if (valid && (u[j] >> bits) == U)
                    atomicAdd(&hist[((u[j] >> (bits - 8)) & 0xFFu) ^ X], 1u);
            }
            __syncthreads();
            if (warp == 0) {
                unsigned rcur = rk;
                const uint4* h4 = reinterpret_cast<const uint4*>(hist) + lane * 2;
                uint4 v0 = h4[0], v1 = h4[1];
                unsigned cc[8] = { v0.x, v0.y, v0.z, v0.w, v1.x, v1.y, v1.z, v1.w };
                unsigned tot = cc[0]+cc[1]+cc[2]+cc[3]+cc[4]+cc[5]+cc[6]+cc[7];
                unsigned s = tot;
#pragma unroll
                for (int off = 1; off <= 16; off <<= 1) {
                    unsigned v = __shfl_down_sync(0xFFFFFFFFu, s, off);
                    if (lane + off < 32) s += v;
                }
                unsigned run = s - tot;
#pragma unroll
                for (int j = 7; j >= 0; --j) {
                    unsigned nr = run + cc[j];
                    if (nr >= rcur && run < rcur) {
                        sb_b    = (unsigned)(lane * 8 + j);
                        sb_rank = rcur - run;
                        sb_m    = cc[j];
                    }
                    run = nr;
                }
            }
            __syncthreads();
            U  = (U << 8) | (sb_b ^ X);
            K  = (K << 8) | sb_b;
            rk = sb_rank;
            mm = sb_m;
            bits -= 8;
        }
        if (bits > 0) {
#pragma unroll
            for (int j = 0; j < 16; ++j) {
                bool valid = (j < 12) || has4;
                if (valid && (u[j] >> bits) == U) {
                    int p = atomicAdd(&gcount, 1);
                    if (p < 64) gbuf[p] = u2k(u[j]);
                }
            }
            __syncthreads();
            if (warp == 0) {
                int n = gcount; if (n > 64) n = 64;
                unsigned ck0 = (lane      < n) ? gbuf[lane]      : 0u;
                unsigned ck1 = (lane + 32 < n) ? gbuf[lane + 32] : 0u;
                bool a0 = (lane < n), a1 = (lane + 32 < n);
                unsigned r = rk;
                unsigned tk = K << bits;
                for (int b = bits - 1; b >= 0; --b) {
                    bool bit0 = ((ck0 >> b) & 1u) != 0u;
                    bool bit1 = ((ck1 >> b) & 1u) != 0u;
                    unsigned c = __popc(__ballot_sync(0xFFFFFFFFu, a0 && bit0))
                               + __popc(__ballot_sync(0xFFFFFFFFu, a1 && bit1));
                    if (c >= r) { a0 = a0 && bit0; a1 = a1 && bit1; tk |= (1u << b); }
                    else        { r -= c; a0 = a0 && !bit0; a1 = a1 && !bit1; }
                }
                if (lane == 0) sb_t = k2f(tk);
            }
        } else {
            if (tid == 0) sb_t = __uint_as_float(U);
        }
        __syncthreads();
    }
    const float t = sb_t;

    // ---- mask + store: float compare ----
    float4* po = reinterpret_cast<float4*>(out + base);
#pragma unroll
    for (int s = 0; s < 4; ++s) {
        int p = tid + s * 256;
        if (s < 3 || has4) {
            float4 o;
            float fx = __uint_as_float(u[4*s+0]);
            float fy = __uint_as_float(u[4*s+1]);
            float fz = __uint_as_float(u[4*s+2]);
            float fw = __uint_as_float(u[4*s+3]);
            o.x = (fx < t) ? fx : 0.0f;
            o.y = (fy < t) ? fy : 0.0f;
            o.z = (fz < t) ? fz : 0.0f;
            o.w = (fw < t) ? fw : 0.0f;
            po[p] = o;
        }
    }
}

extern "C" void kernel_launch(void* const* d_in, const int* in_sizes, int n_in,
                              void* d_out, int out_size) {
    const float* x = (const float*)d_in[0];
    float* out = (float*)d_out;
    int rows = in_sizes[0] / NROW;   // 16384
    wta2d_kernel<<<rows, 256>>>(x, out);
}